// round 1
// baseline (speedup 1.0000x reference)
#include <cuda_runtime.h>
#include <math.h>
#include <stdint.h>

// Problem constants
#define B_DIM 4096
#define NX 512
#define NH 512
#define NY 256
#define KSTATES 8

// GEMM tiling
#define BM 128
#define BN 128
#define BKT 32
#define LDSS (BKT + 4)   // padded smem stride (36 floats): conflict-free frag reads, 16B-aligned float4 cols

// k-major contiguous scratch (device globals: allocation-free)
__device__ float g_scr_h[(size_t)KSTATES * B_DIM * NH];  // 64 MiB
__device__ float g_scr_o[(size_t)KSTATES * B_DIM * NY];  // 32 MiB

__device__ __forceinline__ uint32_t f2tf(float f) {
    uint32_t r;
    asm("cvt.rna.tf32.f32 %0, %1;" : "=r"(r) : "f"(f));
    return r;
}

// C_z[M, ldc] = op( A_z[M, KD] * B_z[N, KD]^T ), tf32 MMA, fp32 accum.
// For KD==1024 the inner dim is split at 512 between (A0,A1) and (B0,B1);
// all row strides are 512. z = blockIdx.z indexes the K=8 states.
template<bool TANH, int KD>
__global__ __launch_bounds__(256)
void gemm_tf32(const float* __restrict__ A0, const float* __restrict__ A1, size_t strideA,
               const float* __restrict__ B0, const float* __restrict__ B1, size_t strideB,
               float* __restrict__ C, size_t strideC, int ldc)
{
    __shared__ uint32_t As[BM][LDSS];
    __shared__ uint32_t Bs[BN][LDSS];

    const int tid  = threadIdx.x;
    const int warp = tid >> 5;
    const int lane = tid & 31;
    const int gid  = lane >> 2;    // group id (0..7)
    const int tg   = lane & 3;     // thread-in-group (0..3)
    const int warpM = warp & 3;    // 4 warps along M
    const int warpN = warp >> 2;   // 2 warps along N

    const int bm = blockIdx.y * BM;
    const int bn = blockIdx.x * BN;
    const int z  = blockIdx.z;

    const float* A0z = A0 + (size_t)z * strideA;
    const float* A1z = A1 + (size_t)z * strideA;
    const float* B0z = B0 + (size_t)z * strideB;
    const float* B1z = B1 + (size_t)z * strideB;
    float* Cz = C + (size_t)z * strideC;

    // global-load assignment: 256 threads cover a 128x32 tile, 4 rows each, float4 cols
    const int lrow = tid >> 3;          // 0..31
    const int lcol = (tid & 7) * 4;     // 0,4,...,28

    float4 ra[4], rb[4];

    auto gload = [&](int k0) {
        const float* Ap = A0z;
        const float* Bp = B0z;
        int kc = k0;
        if (KD == 1024 && k0 >= 512) { Ap = A1z; Bp = B1z; kc = k0 - 512; }
        #pragma unroll
        for (int i = 0; i < 4; ++i) {
            int r = lrow + i * 32;
            ra[i] = *reinterpret_cast<const float4*>(Ap + (size_t)(bm + r) * 512 + kc + lcol);
            rb[i] = *reinterpret_cast<const float4*>(Bp + (size_t)(bn + r) * 512 + kc + lcol);
        }
    };

    auto sstore = [&]() {
        #pragma unroll
        for (int i = 0; i < 4; ++i) {
            int r = lrow + i * 32;
            As[r][lcol + 0] = f2tf(ra[i].x);
            As[r][lcol + 1] = f2tf(ra[i].y);
            As[r][lcol + 2] = f2tf(ra[i].z);
            As[r][lcol + 3] = f2tf(ra[i].w);
            Bs[r][lcol + 0] = f2tf(rb[i].x);
            Bs[r][lcol + 1] = f2tf(rb[i].y);
            Bs[r][lcol + 2] = f2tf(rb[i].z);
            Bs[r][lcol + 3] = f2tf(rb[i].w);
        }
    };

    float acc[2][8][4];
    #pragma unroll
    for (int im = 0; im < 2; ++im)
        #pragma unroll
        for (int in = 0; in < 8; ++in)
            #pragma unroll
            for (int c = 0; c < 4; ++c) acc[im][in][c] = 0.0f;

    gload(0);
    sstore();
    __syncthreads();

    const int nsteps = KD / BKT;
    for (int kt = 0; kt < nsteps; ++kt) {
        if (kt + 1 < nsteps) gload((kt + 1) * BKT);  // overlap next tile loads with compute

        #pragma unroll
        for (int kk = 0; kk < BKT; kk += 8) {
            uint32_t af[2][4];
            #pragma unroll
            for (int im = 0; im < 2; ++im) {
                int mb = warpM * 32 + im * 16 + gid;
                af[im][0] = As[mb][kk + tg];
                af[im][1] = As[mb + 8][kk + tg];
                af[im][2] = As[mb][kk + tg + 4];
                af[im][3] = As[mb + 8][kk + tg + 4];
            }
            #pragma unroll
            for (int in = 0; in < 8; ++in) {
                int nb = warpN * 64 + in * 8 + gid;
                uint32_t bf0 = Bs[nb][kk + tg];
                uint32_t bf1 = Bs[nb][kk + tg + 4];
                #pragma unroll
                for (int im = 0; im < 2; ++im) {
                    asm volatile(
                        "mma.sync.aligned.m16n8k8.row.col.f32.tf32.tf32.f32 "
                        "{%0,%1,%2,%3}, {%4,%5,%6,%7}, {%8,%9}, {%0,%1,%2,%3};\n"
                        : "+f"(acc[im][in][0]), "+f"(acc[im][in][1]),
                          "+f"(acc[im][in][2]), "+f"(acc[im][in][3])
                        : "r"(af[im][0]), "r"(af[im][1]), "r"(af[im][2]), "r"(af[im][3]),
                          "r"(bf0), "r"(bf1));
                }
            }
        }
        __syncthreads();
        if (kt + 1 < nsteps) { sstore(); __syncthreads(); }
    }

    // epilogue: optional tanh, float2 stores (columns are even-aligned)
    #pragma unroll
    for (int im = 0; im < 2; ++im) {
        int r0 = bm + warpM * 32 + im * 16 + gid;
        #pragma unroll
        for (int in = 0; in < 8; ++in) {
            int c0 = bn + warpN * 64 + in * 8 + tg * 2;
            float v0 = acc[im][in][0], v1 = acc[im][in][1];
            float v2 = acc[im][in][2], v3 = acc[im][in][3];
            if (TANH) { v0 = tanhf(v0); v1 = tanhf(v1); v2 = tanhf(v2); v3 = tanhf(v3); }
            *reinterpret_cast<float2*>(Cz + (size_t)r0 * ldc + c0)       = make_float2(v0, v1);
            *reinterpret_cast<float2*>(Cz + (size_t)(r0 + 8) * ldc + c0) = make_float2(v2, v3);
        }
    }
}

// Re-interleave k-major scratch into the reference's K-innermost layout, fusing the
// belief-weighted mix:  out_k8[idx*8 + k] = scr[k][idx],  out_mix[idx] = sum_k pi[b,k]*scr[k][idx]
__global__ __launch_bounds__(256)
void pack_mix(const float* __restrict__ scr, const float* __restrict__ pi,
              float* __restrict__ out_k8, float* __restrict__ out_mix,
              int bshift, size_t plane)
{
    size_t idx = (size_t)blockIdx.x * blockDim.x + threadIdx.x;
    int b = (int)(idx >> bshift);
    float4 p0 = *reinterpret_cast<const float4*>(pi + (size_t)b * 8);
    float4 p1 = *reinterpret_cast<const float4*>(pi + (size_t)b * 8 + 4);

    float v[8];
    #pragma unroll
    for (int k = 0; k < 8; ++k) v[k] = scr[(size_t)k * plane + idx];

    float mix = v[0] * p0.x + v[1] * p0.y + v[2] * p0.z + v[3] * p0.w
              + v[4] * p1.x + v[5] * p1.y + v[6] * p1.z + v[7] * p1.w;

    float4* o = reinterpret_cast<float4*>(out_k8 + idx * 8);
    o[0] = make_float4(v[0], v[1], v[2], v[3]);
    o[1] = make_float4(v[4], v[5], v[6], v[7]);
    out_mix[idx] = mix;
}

extern "C" void kernel_launch(void* const* d_in, const int* in_sizes, int n_in,
                              void* d_out, int out_size)
{
    const float* x     = (const float*)d_in[0];
    const float* h     = (const float*)d_in[1];
    const float* pi    = (const float*)d_in[2];
    const float* W_ih  = (const float*)d_in[3];
    const float* W_hh  = (const float*)d_in[4];
    const float* W_out = (const float*)d_in[5];
    float* out = (float*)d_out;

    float *scr_h, *scr_o;
    cudaGetSymbolAddress((void**)&scr_h, g_scr_h);
    cudaGetSymbolAddress((void**)&scr_o, g_scr_o);

    // output layout: tuple (out, h_mix, out_k, h_k) concatenated, each row-major
    float* o_out  = out;                                   // (B, NY)
    float* o_mix  = o_out  + (size_t)B_DIM * NY;           // (B, NH)
    float* o_outk = o_mix  + (size_t)B_DIM * NH;           // (B, NY, K)
    float* o_hk   = o_outk + (size_t)B_DIM * NY * KSTATES; // (B, NH, K)

    // K1: h_k[z] = tanh([x|h] @ [W_ih[z]|W_hh[z]]^T)  -> scr_h (k-major)
    gemm_tf32<true, 1024><<<dim3(NH / BN, B_DIM / BM, KSTATES), 256>>>(
        x, h, 0,
        W_ih, W_hh, (size_t)NH * NX,
        scr_h, (size_t)B_DIM * NH, NH);

    // K2: out_k[z] = h_k[z] @ W_out^T  -> scr_o (k-major)
    gemm_tf32<false, 512><<<dim3(NY / BN, B_DIM / BM, KSTATES), 256>>>(
        scr_h, scr_h, (size_t)B_DIM * NH,
        W_out, W_out, 0,
        scr_o, (size_t)B_DIM * NY, NY);

    // K3: interleave + h_mix = sum_k pi_k h_k
    pack_mix<<<(B_DIM * NH) / 256, 256>>>(scr_h, pi, o_hk, o_mix, 9, (size_t)B_DIM * NH);

    // K4: interleave + out = sum_k pi_k out_k  (== h_mix @ W_out^T)
    pack_mix<<<(B_DIM * NY) / 256, 256>>>(scr_o, pi, o_outk, o_out, 8, (size_t)B_DIM * NY);
}

// round 3
// speedup vs baseline: 1.3489x; 1.3489x over previous
#include <cuda_runtime.h>
#include <cuda_fp16.h>
#include <math.h>
#include <stdint.h>

// ---------------- problem constants ----------------
#define B_DIM 4096
#define NH 512
#define NY 256
#define KSTATES 8

// ---------------- GEMM tiling ----------------
#define BM 128
#define BN 128
#define BK 64              // halves per k-stage (128 bytes/row)
#define NSTAGE 4
#define STAGE_BYTES 32768  // A 16KB + B 16KB
#define SMEM_BYTES (NSTAGE * STAGE_BYTES)

// ---------------- device scratch (allocation-free) ----------------
__device__ __align__(16) __half g_A16[(size_t)B_DIM * 1024];            // [x|h] fp16
__device__ __align__(16) __half g_B16[(size_t)KSTATES * NH * 1024];     // [W_ih|W_hh] fp16
__device__ __align__(16) __half g_Wo16[(size_t)NY * NH];                // W_out fp16
__device__ __align__(16) __half g_h16[(size_t)KSTATES * B_DIM * NH];    // tanh result fp16 (K2 input)
__device__ float g_scr_h[(size_t)KSTATES * B_DIM * NH];                 // h_k f32, k-major
__device__ float g_scr_o[(size_t)KSTATES * B_DIM * NY];                 // out_k f32, k-major

// ============================================================================
// One-shot fp32 -> fp16 conversion of all GEMM operands
// ============================================================================
#define NA_G (B_DIM * 1024 / 4)
#define NB_G (KSTATES * NH * 1024 / 4)
#define NW_G (NY * NH / 4)

__global__ __launch_bounds__(256)
void cvt_all(const float* __restrict__ x, const float* __restrict__ h,
             const float* __restrict__ W_ih, const float* __restrict__ W_hh,
             const float* __restrict__ W_out,
             __half* __restrict__ A16, __half* __restrict__ B16,
             __half* __restrict__ Wo16)
{
    int idx = blockIdx.x * blockDim.x + threadIdx.x;
    const float* src;
    __half* dst;
    if (idx < NA_G) {
        int d = idx * 4, b = d >> 10, c = d & 1023;
        src = (c < 512) ? (x + (size_t)b * 512 + c) : (h + (size_t)b * 512 + (c - 512));
        dst = A16 + d;
    } else if (idx < NA_G + NB_G) {
        int d = (idx - NA_G) * 4, r = d >> 10, c = d & 1023;
        src = (c < 512) ? (W_ih + (size_t)r * 512 + c) : (W_hh + (size_t)r * 512 + (c - 512));
        dst = B16 + d;
    } else if (idx < NA_G + NB_G + NW_G) {
        int d = (idx - NA_G - NB_G) * 4;
        src = W_out + d;
        dst = Wo16 + d;
    } else {
        return;
    }
    float4 f = *(const float4*)src;
    __half2 lo = __floats2half2_rn(f.x, f.y);
    __half2 hi = __floats2half2_rn(f.z, f.w);
    *(uint2*)dst = make_uint2(*(uint32_t*)&lo, *(uint32_t*)&hi);
}

// ============================================================================
// fp16 mma.sync GEMM: C_z = op( A_z[M,KD] * B_z[N,KD]^T ), f32 accumulate.
// A,B fp16 row-major with row stride KD halves. SW128-style XOR swizzle,
// cp.async 4-stage pipeline, 128x128 CTA tile, 8 warps (4Mx2N), 32x64/warp.
// ============================================================================
template<bool TANH, int KD>
__global__ __launch_bounds__(256)
void gemm_f16(const __half* __restrict__ A, size_t strideA,
              const __half* __restrict__ Bm, size_t strideB,
              float* __restrict__ C, size_t strideC,
              __half* __restrict__ C16, size_t strideC16, int ldc)
{
    extern __shared__ __align__(128) char smem[];
    const int tid = threadIdx.x, wid = tid >> 5, lane = tid & 31;
    const int gid = lane >> 2, tg = lane & 3;
    const int warpM = wid & 3, warpN = wid >> 2;
    const int bm = blockIdx.y * BM, bn = blockIdx.x * BN, z = blockIdx.z;

    const __half* Az = A + (size_t)z * strideA;
    const __half* Bz = Bm + (size_t)z * strideB;

    // cp.async assignment: 2 threads per row, 4 chunks (16B) each
    const int row_ld = wid * 16 + (lane >> 1);
    const int cb = (lane & 1) * 4;

    uint32_t sbase;
    asm("{ .reg .u64 t; cvta.to.shared.u64 t, %1; cvt.u32.u64 %0, t; }"
        : "=r"(sbase) : "l"(smem));

    auto issue = [&](int kt, int bi) {
        const uint32_t sA = sbase + bi * STAGE_BYTES;
        const __half* ga = Az + (size_t)(bm + row_ld) * KD + kt * BK;
        const __half* gb = Bz + (size_t)(bn + row_ld) * KD + kt * BK;
        #pragma unroll
        for (int i = 0; i < 4; ++i) {
            int c = cb + i;
            uint32_t sw = (uint32_t)row_ld * 128 + (uint32_t)((c ^ (row_ld & 7)) * 16);
            asm volatile("cp.async.cg.shared.global [%0], [%1], 16;"
                         :: "r"(sA + sw), "l"(ga + c * 8));
            asm volatile("cp.async.cg.shared.global [%0], [%1], 16;"
                         :: "r"(sA + 16384 + sw), "l"(gb + c * 8));
        }
    };

    float acc[2][8][4];
    #pragma unroll
    for (int im = 0; im < 2; ++im)
        #pragma unroll
        for (int in = 0; in < 8; ++in)
            #pragma unroll
            for (int q = 0; q < 4; ++q) acc[im][in][q] = 0.0f;

    constexpr int NSTEPS = KD / BK;

    #pragma unroll
    for (int s = 0; s < NSTAGE - 1; ++s) {
        issue(s, s);
        asm volatile("cp.async.commit_group;" ::: "memory");
    }

    for (int it = 0; it < NSTEPS; ++it) {
        const int bi = it % NSTAGE;
        asm volatile("cp.async.wait_group %0;" :: "n"(NSTAGE - 2) : "memory");
        __syncthreads();

        const char* sA = smem + bi * STAGE_BYTES;
        const char* sB = sA + 16384;

        #pragma unroll
        for (int kk = 0; kk < 4; ++kk) {
            const int ch0 = (2 * kk) ^ gid;
            const int ch1 = (2 * kk + 1) ^ gid;
            uint32_t a[2][4];
            #pragma unroll
            for (int im = 0; im < 2; ++im) {
                const int r0 = warpM * 32 + im * 16 + gid;
                a[im][0] = *(const uint32_t*)(sA + r0 * 128 + ch0 * 16 + tg * 4);
                a[im][1] = *(const uint32_t*)(sA + (r0 + 8) * 128 + ch0 * 16 + tg * 4);
                a[im][2] = *(const uint32_t*)(sA + r0 * 128 + ch1 * 16 + tg * 4);
                a[im][3] = *(const uint32_t*)(sA + (r0 + 8) * 128 + ch1 * 16 + tg * 4);
            }
            #pragma unroll
            for (int in = 0; in < 8; ++in) {
                const int nb = warpN * 64 + in * 8 + gid;
                uint32_t b0 = *(const uint32_t*)(sB + nb * 128 + ch0 * 16 + tg * 4);
                uint32_t b1 = *(const uint32_t*)(sB + nb * 128 + ch1 * 16 + tg * 4);
                #pragma unroll
                for (int im = 0; im < 2; ++im) {
                    asm volatile(
                        "mma.sync.aligned.m16n8k16.row.col.f32.f16.f16.f32 "
                        "{%0,%1,%2,%3}, {%4,%5,%6,%7}, {%8,%9}, {%0,%1,%2,%3};\n"
                        : "+f"(acc[im][in][0]), "+f"(acc[im][in][1]),
                          "+f"(acc[im][in][2]), "+f"(acc[im][in][3])
                        : "r"(a[im][0]), "r"(a[im][1]), "r"(a[im][2]), "r"(a[im][3]),
                          "r"(b0), "r"(b1));
                }
            }
        }
        __syncthreads();

        const int nx = it + NSTAGE - 1;
        if (nx < NSTEPS) issue(nx, nx % NSTAGE);
        asm volatile("cp.async.commit_group;" ::: "memory");
    }

    // epilogue: f32 stores (+ optional tanh and fp16 mirror for K2 input)
    float* Cz = C + (size_t)z * strideC;
    __half* C16z = C16 ? (C16 + (size_t)z * strideC16) : nullptr;
    #pragma unroll
    for (int im = 0; im < 2; ++im) {
        const int r0 = bm + warpM * 32 + im * 16 + gid;
        #pragma unroll
        for (int in = 0; in < 8; ++in) {
            const int c0 = bn + warpN * 64 + in * 8 + tg * 2;
            float v0 = acc[im][in][0], v1 = acc[im][in][1];
            float v2 = acc[im][in][2], v3 = acc[im][in][3];
            if (TANH) { v0 = tanhf(v0); v1 = tanhf(v1); v2 = tanhf(v2); v3 = tanhf(v3); }
            *(float2*)(Cz + (size_t)r0 * ldc + c0)       = make_float2(v0, v1);
            *(float2*)(Cz + (size_t)(r0 + 8) * ldc + c0) = make_float2(v2, v3);
            if (C16z) {
                __half2 h01 = __floats2half2_rn(v0, v1);
                __half2 h23 = __floats2half2_rn(v2, v3);
                *(uint32_t*)(C16z + (size_t)r0 * ldc + c0)       = *(uint32_t*)&h01;
                *(uint32_t*)(C16z + (size_t)(r0 + 8) * ldc + c0) = *(uint32_t*)&h23;
            }
        }
    }
}

// ============================================================================
// Re-interleave k-major scratch into K-innermost layout + belief-weighted mix
// ============================================================================
__global__ __launch_bounds__(256)
void pack_mix(const float* __restrict__ scr, const float* __restrict__ pi,
              float* __restrict__ out_k8, float* __restrict__ out_mix,
              int bshift, size_t plane)
{
    size_t idx = (size_t)blockIdx.x * blockDim.x + threadIdx.x;
    int b = (int)(idx >> bshift);
    float4 p0 = *reinterpret_cast<const float4*>(pi + (size_t)b * 8);
    float4 p1 = *reinterpret_cast<const float4*>(pi + (size_t)b * 8 + 4);

    float v[8];
    #pragma unroll
    for (int k = 0; k < 8; ++k) v[k] = scr[(size_t)k * plane + idx];

    float mix = v[0] * p0.x + v[1] * p0.y + v[2] * p0.z + v[3] * p0.w
              + v[4] * p1.x + v[5] * p1.y + v[6] * p1.z + v[7] * p1.w;

    float4* o = reinterpret_cast<float4*>(out_k8 + idx * 8);
    o[0] = make_float4(v[0], v[1], v[2], v[3]);
    o[1] = make_float4(v[4], v[5], v[6], v[7]);
    out_mix[idx] = mix;
}

extern "C" void kernel_launch(void* const* d_in, const int* in_sizes, int n_in,
                              void* d_out, int out_size)
{
    const float* x     = (const float*)d_in[0];
    const float* h     = (const float*)d_in[1];
    const float* pi    = (const float*)d_in[2];
    const float* W_ih  = (const float*)d_in[3];
    const float* W_hh  = (const float*)d_in[4];
    const float* W_out = (const float*)d_in[5];
    float* out = (float*)d_out;

    __half *A16, *B16, *Wo16, *h16;
    float *scr_h, *scr_o;
    cudaGetSymbolAddress((void**)&A16, g_A16);
    cudaGetSymbolAddress((void**)&B16, g_B16);
    cudaGetSymbolAddress((void**)&Wo16, g_Wo16);
    cudaGetSymbolAddress((void**)&h16, g_h16);
    cudaGetSymbolAddress((void**)&scr_h, g_scr_h);
    cudaGetSymbolAddress((void**)&scr_o, g_scr_o);

    // output layout: tuple (out, h_mix, out_k, h_k) concatenated, each row-major
    float* o_out  = out;                                   // (B, NY)
    float* o_mix  = o_out  + (size_t)B_DIM * NY;           // (B, NH)
    float* o_outk = o_mix  + (size_t)B_DIM * NH;           // (B, NY, K)
    float* o_hk   = o_outk + (size_t)B_DIM * NY * KSTATES; // (B, NH, K)

    cudaFuncSetAttribute(gemm_f16<true, 1024>,
                         cudaFuncAttributeMaxDynamicSharedMemorySize, SMEM_BYTES);
    cudaFuncSetAttribute(gemm_f16<false, 512>,
                         cudaFuncAttributeMaxDynamicSharedMemorySize, SMEM_BYTES);

    // K0: convert operands to fp16 (A16 = [x|h], B16 = [W_ih|W_hh], Wo16)
    cvt_all<<<(NA_G + NB_G + NW_G + 255) / 256, 256>>>(
        x, h, W_ih, W_hh, W_out, A16, B16, Wo16);

    // K1: h_k[z] = tanh(A16 @ B16[z]^T) -> scr_h (f32) + h16 (fp16)
    gemm_f16<true, 1024><<<dim3(NH / BN, B_DIM / BM, KSTATES), 256, SMEM_BYTES>>>(
        A16, 0,
        B16, (size_t)NH * 1024,
        scr_h, (size_t)B_DIM * NH,
        h16, (size_t)B_DIM * NH, NH);

    // K2: out_k[z] = h16[z] @ Wo16^T -> scr_o (f32)
    gemm_f16<false, 512><<<dim3(NY / BN, B_DIM / BM, KSTATES), 256, SMEM_BYTES>>>(
        h16, (size_t)B_DIM * NH,
        Wo16, 0,
        scr_o, (size_t)B_DIM * NY,
        nullptr, 0, NY);

    // K3/K4: interleave + belief mixes
    pack_mix<<<(B_DIM * NH) / 256, 256>>>(scr_h, pi, o_hk, o_mix, 9, (size_t)B_DIM * NH);
    pack_mix<<<(B_DIM * NY) / 256, 256>>>(scr_o, pi, o_outk, o_out, 8, (size_t)B_DIM * NY);
}

// round 4
// speedup vs baseline: 1.4867x; 1.1021x over previous
#include <cuda_runtime.h>
#include <cuda_fp16.h>
#include <math.h>
#include <stdint.h>

// ---------------- problem constants ----------------
#define B_DIM 4096
#define NH 512
#define NY 256
#define KSTATES 8

// ---------------- GEMM tiling ----------------
#define BM 128
#define BN 128
#define BK 64              // halves per k-stage (128 bytes/row)
#define NSTAGE 4
#define STAGE_BYTES 32768  // A 16KB + B 16KB
#define SMEM_BYTES (NSTAGE * STAGE_BYTES)
#define EP_LDS 132         // epilogue staging row stride (halves)

// ---------------- device scratch (allocation-free) ----------------
__device__ __align__(16) __half g_A16[(size_t)B_DIM * 1024];             // [x|h] fp16
__device__ __align__(16) __half g_B16[(size_t)NH * KSTATES * 1024];      // Bv interleaved rows (n*8+k)
__device__ __align__(16) __half g_Wo16[(size_t)NY * NH];                 // W_out fp16
__device__ __align__(16) __half g_h16[(size_t)KSTATES * B_DIM * NH];     // tanh(h_k) fp16, k-major
__device__ float g_scr_o[(size_t)KSTATES * B_DIM * NY];                  // out_k f32, k-major

// ============================================================================
// One-shot fp32 -> fp16 conversion / packing of all GEMM operands
// ============================================================================
#define NA_G (B_DIM * 1024 / 4)
#define NB_G (NH * KSTATES * 1024 / 4)
#define NW_G (NY * NH / 4)

__global__ __launch_bounds__(256)
void cvt_all(const float* __restrict__ x, const float* __restrict__ h,
             const float* __restrict__ W_ih, const float* __restrict__ W_hh,
             const float* __restrict__ W_out,
             __half* __restrict__ A16, __half* __restrict__ B16,
             __half* __restrict__ Wo16)
{
    int idx = blockIdx.x * blockDim.x + threadIdx.x;
    const float* src;
    __half* dst;
    if (idx < NA_G) {
        int d = idx * 4, b = d >> 10, c = d & 1023;
        src = (c < 512) ? (x + (size_t)b * 512 + c) : (h + (size_t)b * 512 + (c - 512));
        dst = A16 + d;
    } else if (idx < NA_G + NB_G) {
        int d = (idx - NA_G) * 4;
        int row = d >> 10, c = d & 1023;
        int n = row >> 3, k = row & 7;                  // interleaved row = n*8+k
        const float* Wb = (c < 512) ? (W_ih + (size_t)((k * 512) + n) * 512 + c)
                                    : (W_hh + (size_t)((k * 512) + n) * 512 + (c - 512));
        src = Wb;
        dst = B16 + d;
    } else if (idx < NA_G + NB_G + NW_G) {
        int d = (idx - NA_G - NB_G) * 4;
        src = W_out + d;
        dst = Wo16 + d;
    } else {
        return;
    }
    float4 f = *(const float4*)src;
    __half2 lo = __floats2half2_rn(f.x, f.y);
    __half2 hi = __floats2half2_rn(f.z, f.w);
    *(uint2*)dst = make_uint2(*(uint32_t*)&lo, *(uint32_t*)&hi);
}

// ---------------- mma / ldmatrix helpers ----------------
static __device__ __forceinline__ void ldsm4(uint32_t& r0, uint32_t& r1,
                                             uint32_t& r2, uint32_t& r3, uint32_t addr) {
    asm volatile("ldmatrix.sync.aligned.m8n8.x4.shared.b16 {%0,%1,%2,%3}, [%4];"
                 : "=r"(r0), "=r"(r1), "=r"(r2), "=r"(r3) : "r"(addr));
}
static __device__ __forceinline__ void mma16816(float (&c)[4], const uint32_t (&a)[4],
                                                uint32_t b0, uint32_t b1) {
    asm volatile(
        "mma.sync.aligned.m16n8k16.row.col.f32.f16.f16.f32 "
        "{%0,%1,%2,%3}, {%4,%5,%6,%7}, {%8,%9}, {%0,%1,%2,%3};\n"
        : "+f"(c[0]), "+f"(c[1]), "+f"(c[2]), "+f"(c[3])
        : "r"(a[0]), "r"(a[1]), "r"(a[2]), "r"(a[3]), "r"(b0), "r"(b1));
}

// ============================================================================
// Shared mainloop: acc[2][8][4] += A_tile(128,KD) * B_tile(128,KD)^T
// fp16 operands, SW128-style XOR swizzle, cp.async pipeline, ldmatrix frags.
// ============================================================================
template<int KD>
static __device__ __forceinline__
void run_mainloop(const __half* __restrict__ Az, const __half* __restrict__ Bz,
                  uint32_t sbase, float (&acc)[2][8][4], int bm, int bn)
{
    const int tid = threadIdx.x, wid = tid >> 5, lane = tid & 31;
    const int warpM = wid & 3, warpN = wid >> 2;

    // cp.async: 2 threads per row, 4 x 16B chunks each
    const int row_ld = wid * 16 + (lane >> 1);
    const int cb = (lane & 1) * 4;

    auto issue = [&](int kt, int bi) {
        const uint32_t sA = sbase + bi * STAGE_BYTES;
        const __half* ga = Az + (size_t)(bm + row_ld) * KD + kt * BK;
        const __half* gb = Bz + (size_t)(bn + row_ld) * KD + kt * BK;
        #pragma unroll
        for (int i = 0; i < 4; ++i) {
            int c = cb + i;
            uint32_t sw = (uint32_t)row_ld * 128 + (uint32_t)((c ^ (row_ld & 7)) * 16);
            asm volatile("cp.async.cg.shared.global [%0], [%1], 16;"
                         :: "r"(sA + sw), "l"(ga + c * 8));
            asm volatile("cp.async.cg.shared.global [%0], [%1], 16;"
                         :: "r"(sA + 16384 + sw), "l"(gb + c * 8));
        }
    };

    // ldmatrix lane geometry
    const int rwi  = lane & 7;
    const int hi8  = (lane >> 3) & 1;
    const int hi16 = lane >> 4;
    const int rowA0 = warpM * 32 + hi8 * 8 + rwi;   // +im*16
    const int rowB0 = warpN * 64 + hi8 * 8 + rwi;   // +j*16

    constexpr int NSTEPS = KD / BK;

    #pragma unroll
    for (int s = 0; s < NSTAGE - 1; ++s) {
        issue(s, s);
        asm volatile("cp.async.commit_group;" ::: "memory");
    }

    for (int it = 0; it < NSTEPS; ++it) {
        asm volatile("cp.async.wait_group %0;" :: "n"(NSTAGE - 2) : "memory");
        __syncthreads();

        const int nx = it + NSTAGE - 1;
        if (nx < NSTEPS) issue(nx, nx & (NSTAGE - 1));
        asm volatile("cp.async.commit_group;" ::: "memory");

        const uint32_t sA = sbase + (it & (NSTAGE - 1)) * STAGE_BYTES;
        const uint32_t sB = sA + 16384;

        #pragma unroll
        for (int kk = 0; kk < 4; ++kk) {
            const uint32_t chx = (uint32_t)(((2 * kk + hi16) ^ rwi) << 4);
            uint32_t a[2][4];
            #pragma unroll
            for (int im = 0; im < 2; ++im)
                ldsm4(a[im][0], a[im][1], a[im][2], a[im][3],
                      sA + (uint32_t)(rowA0 + im * 16) * 128 + chx);
            #pragma unroll
            for (int j = 0; j < 4; ++j) {
                uint32_t q0, q1, q2, q3;
                ldsm4(q0, q1, q2, q3, sB + (uint32_t)(rowB0 + j * 16) * 128 + chx);
                #pragma unroll
                for (int im = 0; im < 2; ++im) {
                    mma16816(acc[im][2 * j],     a[im], q0, q2);
                    mma16816(acc[im][2 * j + 1], a[im], q1, q3);
                }
            }
        }
    }
}

// ============================================================================
// K1: big GEMM (4096 x 4096 x 1024). Output cols are (n*8+k) interleaved ==
// o_hk layout. Epilogue: tanh -> o_hk f32; quad-shuffle pi-mix -> o_mix;
// smem restage -> h16 (k-major fp16, K2's A input).
// ============================================================================
__global__ __launch_bounds__(256, 1)
void gemm_k1(const __half* __restrict__ A, const __half* __restrict__ Bv,
             const float* __restrict__ pi,
             float* __restrict__ o_hk, float* __restrict__ o_mix,
             __half* __restrict__ h16)
{
    extern __shared__ __align__(128) char smem[];
    uint32_t sbase;
    asm("{ .reg .u64 t; cvta.to.shared.u64 t, %1; cvt.u32.u64 %0, t; }"
        : "=r"(sbase) : "l"(smem));

    const int tid = threadIdx.x, wid = tid >> 5, lane = tid & 31;
    const int gid = lane >> 2, tg = lane & 3;
    const int warpM = wid & 3, warpN = wid >> 2;
    const int bm = blockIdx.y * BM, bn = blockIdx.x * BN;

    float acc[2][8][4];
    #pragma unroll
    for (int im = 0; im < 2; ++im)
        #pragma unroll
        for (int in = 0; in < 8; ++in)
            #pragma unroll
            for (int q = 0; q < 4; ++q) acc[im][in][q] = 0.0f;

    run_mainloop<1024>(A, Bv, sbase, acc, bm, bn);

    // ---------- epilogue ----------
    __half* ep = (__half*)smem;          // 128 x EP_LDS staging (overlays stage 0/1)
    const int n0 = bn >> 3;              // global n base for this CTA (16 n's)

    #pragma unroll
    for (int im = 0; im < 2; ++im) {
        const int rA = bm + warpM * 32 + im * 16 + gid;
        const float2 pA = *(const float2*)(pi + (size_t)rA * 8 + tg * 2);
        const float2 pB = *(const float2*)(pi + (size_t)(rA + 8) * 8 + tg * 2);
        #pragma unroll
        for (int in = 0; in < 8; ++in) {
            const int c0 = bn + warpN * 64 + in * 8 + tg * 2;
            float v0 = tanhf(acc[im][in][0]);
            float v1 = tanhf(acc[im][in][1]);
            float v2 = tanhf(acc[im][in][2]);
            float v3 = tanhf(acc[im][in][3]);

            *(float2*)(o_hk + (size_t)rA * 4096 + c0)       = make_float2(v0, v1);
            *(float2*)(o_hk + (size_t)(rA + 8) * 4096 + c0) = make_float2(v2, v3);

            float m0 = v0 * pA.x + v1 * pA.y;
            float m1 = v2 * pB.x + v3 * pB.y;
            m0 += __shfl_xor_sync(0xFFFFFFFFu, m0, 1);
            m0 += __shfl_xor_sync(0xFFFFFFFFu, m0, 2);
            m1 += __shfl_xor_sync(0xFFFFFFFFu, m1, 1);
            m1 += __shfl_xor_sync(0xFFFFFFFFu, m1, 2);
            if (tg == 0) {
                const int ng = n0 + warpN * 8 + in;
                o_mix[(size_t)rA * 512 + ng]       = m0;
                o_mix[(size_t)(rA + 8) * 512 + ng] = m1;
            }

            const int rl = warpM * 32 + im * 16 + gid;
            const int cl = warpN * 64 + in * 8 + tg * 2;
            __half2 h01 = __floats2half2_rn(v0, v1);
            __half2 h23 = __floats2half2_rn(v2, v3);
            *(__half2*)(ep + (size_t)rl * EP_LDS + cl)       = h01;
            *(__half2*)(ep + (size_t)(rl + 8) * EP_LDS + cl) = h23;
        }
    }
    __syncthreads();

    // restage to h16 k-major: warp wid owns state k = wid
    {
        const int kst = wid;
        __half* plane = h16 + (size_t)kst * ((size_t)B_DIM * 512);
        const int rr = lane >> 3;       // 0..3 rows
        const int nn = lane & 7;        // n-pair index 0..7 -> n_local 2nn, 2nn+1
        #pragma unroll
        for (int i = 0; i < 32; ++i) {
            const int row = i * 4 + rr;
            __half h0 = ep[(size_t)row * EP_LDS + (2 * nn) * 8 + kst];
            __half h1 = ep[(size_t)row * EP_LDS + (2 * nn + 1) * 8 + kst];
            *(__half2*)(plane + (size_t)(bm + row) * 512 + n0 + 2 * nn) =
                __halves2half2(h0, h1);
        }
    }
}

// ============================================================================
// K2: per-state GEMM out_k[z] = h16[z] @ Wo16^T -> scr_o (k-major f32)
// ============================================================================
__global__ __launch_bounds__(256, 1)
void gemm_k2(const __half* __restrict__ h16, const __half* __restrict__ Wo,
             float* __restrict__ scr_o)
{
    extern __shared__ __align__(128) char smem[];
    uint32_t sbase;
    asm("{ .reg .u64 t; cvta.to.shared.u64 t, %1; cvt.u32.u64 %0, t; }"
        : "=r"(sbase) : "l"(smem));

    const int tid = threadIdx.x, wid = tid >> 5, lane = tid & 31;
    const int gid = lane >> 2, tg = lane & 3;
    const int warpM = wid & 3, warpN = wid >> 2;
    const int bm = blockIdx.y * BM, bn = blockIdx.x * BN, z = blockIdx.z;

    const __half* Az = h16 + (size_t)z * ((size_t)B_DIM * 512);
    float* Cz = scr_o + (size_t)z * ((size_t)B_DIM * 256);

    float acc[2][8][4];
    #pragma unroll
    for (int im = 0; im < 2; ++im)
        #pragma unroll
        for (int in = 0; in < 8; ++in)
            #pragma unroll
            for (int q = 0; q < 4; ++q) acc[im][in][q] = 0.0f;

    run_mainloop<512>(Az, Wo, sbase, acc, bm, bn);

    #pragma unroll
    for (int im = 0; im < 2; ++im) {
        const int r0 = bm + warpM * 32 + im * 16 + gid;
        #pragma unroll
        for (int in = 0; in < 8; ++in) {
            const int c0 = bn + warpN * 64 + in * 8 + tg * 2;
            *(float2*)(Cz + (size_t)r0 * 256 + c0) =
                make_float2(acc[im][in][0], acc[im][in][1]);
            *(float2*)(Cz + (size_t)(r0 + 8) * 256 + c0) =
                make_float2(acc[im][in][2], acc[im][in][3]);
        }
    }
}

// ============================================================================
// Re-interleave k-major scr_o into K-innermost out_k + belief-weighted out
// ============================================================================
__global__ __launch_bounds__(256)
void pack_mix(const float* __restrict__ scr, const float* __restrict__ pi,
              float* __restrict__ out_k8, float* __restrict__ out_mix,
              int bshift, size_t plane)
{
    size_t idx = (size_t)blockIdx.x * blockDim.x + threadIdx.x;
    int b = (int)(idx >> bshift);
    float4 p0 = *reinterpret_cast<const float4*>(pi + (size_t)b * 8);
    float4 p1 = *reinterpret_cast<const float4*>(pi + (size_t)b * 8 + 4);

    float v[8];
    #pragma unroll
    for (int k = 0; k < 8; ++k) v[k] = scr[(size_t)k * plane + idx];

    float mix = v[0] * p0.x + v[1] * p0.y + v[2] * p0.z + v[3] * p0.w
              + v[4] * p1.x + v[5] * p1.y + v[6] * p1.z + v[7] * p1.w;

    float4* o = reinterpret_cast<float4*>(out_k8 + idx * 8);
    o[0] = make_float4(v[0], v[1], v[2], v[3]);
    o[1] = make_float4(v[4], v[5], v[6], v[7]);
    out_mix[idx] = mix;
}

extern "C" void kernel_launch(void* const* d_in, const int* in_sizes, int n_in,
                              void* d_out, int out_size)
{
    const float* x     = (const float*)d_in[0];
    const float* h     = (const float*)d_in[1];
    const float* pi    = (const float*)d_in[2];
    const float* W_ih  = (const float*)d_in[3];
    const float* W_hh  = (const float*)d_in[4];
    const float* W_out = (const float*)d_in[5];
    float* out = (float*)d_out;

    __half *A16, *B16, *Wo16, *h16;
    float *scr_o;
    cudaGetSymbolAddress((void**)&A16, g_A16);
    cudaGetSymbolAddress((void**)&B16, g_B16);
    cudaGetSymbolAddress((void**)&Wo16, g_Wo16);
    cudaGetSymbolAddress((void**)&h16, g_h16);
    cudaGetSymbolAddress((void**)&scr_o, g_scr_o);

    // output layout: tuple (out, h_mix, out_k, h_k) concatenated, each row-major
    float* o_out  = out;                                   // (B, NY)
    float* o_mix  = o_out  + (size_t)B_DIM * NY;           // (B, NH)
    float* o_outk = o_mix  + (size_t)B_DIM * NH;           // (B, NY, K)
    float* o_hk   = o_outk + (size_t)B_DIM * NY * KSTATES; // (B, NH, K)

    cudaFuncSetAttribute(gemm_k1, cudaFuncAttributeMaxDynamicSharedMemorySize, SMEM_BYTES);
    cudaFuncSetAttribute(gemm_k2, cudaFuncAttributeMaxDynamicSharedMemorySize, SMEM_BYTES);

    // K0: fp16 operand packing (A16=[x|h], B16=interleaved Bv, Wo16)
    cvt_all<<<(NA_G + NB_G + NW_G + 255) / 256, 256>>>(
        x, h, W_ih, W_hh, W_out, A16, B16, Wo16);

    // K1: big GEMM -> o_hk (direct) + o_mix + h16
    gemm_k1<<<dim3(4096 / BN, B_DIM / BM), 256, SMEM_BYTES>>>(
        A16, B16, pi, o_hk, o_mix, h16);

    // K2: out_k per state -> scr_o
    gemm_k2<<<dim3(NY / BN, B_DIM / BM, KSTATES), 256, SMEM_BYTES>>>(
        h16, Wo16, scr_o);

    // K3: interleave + out = sum_k pi_k out_k
    pack_mix<<<(B_DIM * NY) / 256, 256>>>(scr_o, pi, o_outk, o_out, 8, (size_t)B_DIM * NY);
}